// round 1
// baseline (speedup 1.0000x reference)
#include <cuda_runtime.h>
#include <cstdint>

#define NN 60000
#define EE 600000
#define DD 128
#define SLOPE 0.01f
#define SBLK 512          // stats partial blocks
#define SCANB 59          // ceil(60000/1024)

// ---------------- device scratch (static, no allocation) ----------------
__device__ int   g_is64;
__device__ int   g_cnt[NN];
__device__ int   g_incl[NN];
__device__ int   g_part[64];
__device__ int   g_rowstart[NN + 1];
__device__ int   g_next[NN];
__device__ int   g_srcidx[EE];
__device__ float g_dinv[NN];
__device__ float g_xw[(size_t)NN * DD];
__device__ float g_h[(size_t)NN * DD];
__device__ double g_bsum[SBLK * DD];
__device__ double g_bsq[SBLK * DD];
__device__ float g_scale[DD];
__device__ float g_shift[DD];

// ---------------- edge dtype handling ----------------
__global__ void k_detect(const void* ei) {
    if (blockIdx.x == 0 && threadIdx.x == 0) {
        const long long* q = (const long long*)ei;
        int ok = 1;
        for (int i = 0; i < 256; i++) {
            long long v = q[i];
            if (v < 0 || v >= NN) { ok = 0; break; }
        }
        g_is64 = ok;
    }
}

__device__ __forceinline__ int edge_at(const void* p, int idx, int is64) {
    return is64 ? (int)((const long long*)p)[idx] : ((const int*)p)[idx];
}

// ---------------- degree + CSR build ----------------
__global__ void k_zero_cnt() {
    int i = blockIdx.x * blockDim.x + threadIdx.x;
    if (i < NN) g_cnt[i] = 0;
}

__global__ void k_hist(const void* ei) {
    int e = blockIdx.x * blockDim.x + threadIdx.x;
    if (e < EE) {
        int d = edge_at(ei, EE + e, g_is64);
        atomicAdd(&g_cnt[d], 1);
    }
}

__global__ void k_dinv() {
    int i = blockIdx.x * blockDim.x + threadIdx.x;
    if (i < NN) g_dinv[i] = rsqrtf((float)(g_cnt[i] + 1)); // +1 self loop
}

__global__ void k_scan1() {
    __shared__ int s[1024];
    int i = blockIdx.x * 1024 + threadIdx.x;
    int x = (i < NN) ? g_cnt[i] : 0;
    s[threadIdx.x] = x;
    __syncthreads();
    for (int off = 1; off < 1024; off <<= 1) {
        int v = (threadIdx.x >= off) ? s[threadIdx.x - off] : 0;
        __syncthreads();
        s[threadIdx.x] += v;
        __syncthreads();
    }
    if (i < NN) g_incl[i] = s[threadIdx.x];
    if (threadIdx.x == 1023) g_part[blockIdx.x] = s[1023];
}

__global__ void k_scan2(int nb) {
    if (threadIdx.x == 0 && blockIdx.x == 0) {
        int run = 0;
        for (int b = 0; b < nb; b++) { int t = g_part[b]; g_part[b] = run; run += t; }
    }
}

__global__ void k_scan3() {
    int i = blockIdx.x * blockDim.x + threadIdx.x;
    if (i < NN) {
        int rs = g_incl[i] - g_cnt[i] + g_part[i >> 10];
        g_rowstart[i] = rs;
        g_next[i] = rs;
    }
    if (i == 0) g_rowstart[NN] = EE;
}

__global__ void k_fill(const void* ei) {
    int e = blockIdx.x * blockDim.x + threadIdx.x;
    if (e < EE) {
        int is64 = g_is64;
        int s = edge_at(ei, e, is64);
        int d = edge_at(ei, EE + e, is64);
        int pos = atomicAdd(&g_next[d], 1);
        g_srcidx[pos] = s;
    }
}

// ---------------- GEMM: C[M,128] = f(A)[M,128] @ W[128,128] ----------------
// f(A) optionally applies per-feature affine (BN of previous layer) + LeakyReLU,
// fused into the A-tile load.
__global__ __launch_bounds__(256) void k_gemm(
    const float* __restrict__ A, const float* __restrict__ W,
    float* __restrict__ C,
    const float* __restrict__ scale, const float* __restrict__ shift, int act)
{
    __shared__ float As[8][128];
    __shared__ float Ws[8][128];
    int t = threadIdx.x;
    int r0 = blockIdx.x * 128;
    int ty = t >> 4, tx = t & 15;
    int arow = t >> 1, ahalf = t & 1;
    int wrow = t >> 5, wcol = (t & 31) * 4;

    float acc[8][8];
#pragma unroll
    for (int i = 0; i < 8; i++)
#pragma unroll
        for (int j = 0; j < 8; j++) acc[i][j] = 0.0f;

    for (int k0 = 0; k0 < 128; k0 += 8) {
        // load A tile 128x8 (transposed into As[k][row]) with fused BN/act
        float4 av = make_float4(0.f, 0.f, 0.f, 0.f);
        int gr = r0 + arow;
        int c0 = k0 + ahalf * 4;
        if (gr < NN)
            av = *reinterpret_cast<const float4*>(A + (size_t)gr * DD + c0);
        if (scale) {
            av.x = av.x * scale[c0 + 0] + shift[c0 + 0];
            av.y = av.y * scale[c0 + 1] + shift[c0 + 1];
            av.z = av.z * scale[c0 + 2] + shift[c0 + 2];
            av.w = av.w * scale[c0 + 3] + shift[c0 + 3];
            if (act) {
                av.x = av.x >= 0.f ? av.x : SLOPE * av.x;
                av.y = av.y >= 0.f ? av.y : SLOPE * av.y;
                av.z = av.z >= 0.f ? av.z : SLOPE * av.z;
                av.w = av.w >= 0.f ? av.w : SLOPE * av.w;
            }
        }
        As[ahalf * 4 + 0][arow] = av.x;
        As[ahalf * 4 + 1][arow] = av.y;
        As[ahalf * 4 + 2][arow] = av.z;
        As[ahalf * 4 + 3][arow] = av.w;

        // load W tile 8x128
        float4 wv = *reinterpret_cast<const float4*>(W + (size_t)(k0 + wrow) * DD + wcol);
        *reinterpret_cast<float4*>(&Ws[wrow][wcol]) = wv;
        __syncthreads();

#pragma unroll
        for (int kk = 0; kk < 8; kk++) {
            float a[8], b[8];
            reinterpret_cast<float4*>(a)[0] = *reinterpret_cast<const float4*>(&As[kk][ty * 8]);
            reinterpret_cast<float4*>(a)[1] = *reinterpret_cast<const float4*>(&As[kk][ty * 8 + 4]);
            reinterpret_cast<float4*>(b)[0] = *reinterpret_cast<const float4*>(&Ws[kk][tx * 8]);
            reinterpret_cast<float4*>(b)[1] = *reinterpret_cast<const float4*>(&Ws[kk][tx * 8 + 4]);
#pragma unroll
            for (int i = 0; i < 8; i++)
#pragma unroll
                for (int j = 0; j < 8; j++)
                    acc[i][j] = fmaf(a[i], b[j], acc[i][j]);
        }
        __syncthreads();
    }

#pragma unroll
    for (int i = 0; i < 8; i++) {
        int gr = r0 + ty * 8 + i;
        if (gr < NN) {
            *reinterpret_cast<float4*>(C + (size_t)gr * DD + tx * 8) =
                make_float4(acc[i][0], acc[i][1], acc[i][2], acc[i][3]);
            *reinterpret_cast<float4*>(C + (size_t)gr * DD + tx * 8 + 4) =
                make_float4(acc[i][4], acc[i][5], acc[i][6], acc[i][7]);
        }
    }
}

// ---------------- aggregation: warp per node, CSR gather ----------------
__global__ __launch_bounds__(256) void k_agg(
    const float* __restrict__ xw, float* __restrict__ outp)
{
    int w = (blockIdx.x * blockDim.x + threadIdx.x) >> 5;
    int lane = threadIdx.x & 31;
    if (w >= NN) return;
    float di = g_dinv[w];

    // self loop: coef = dinv^2
    float4 acc = __ldg(reinterpret_cast<const float4*>(xw + (size_t)w * DD) + lane);
    float cself = di * di;
    acc.x *= cself; acc.y *= cself; acc.z *= cself; acc.w *= cself;

    int beg = g_rowstart[w], end = g_rowstart[w + 1];
    int i = beg;
    for (; i + 1 < end; i += 2) {
        int s0 = g_srcidx[i], s1 = g_srcidx[i + 1];
        float c0 = di * g_dinv[s0];
        float c1 = di * g_dinv[s1];
        float4 v0 = __ldg(reinterpret_cast<const float4*>(xw + (size_t)s0 * DD) + lane);
        float4 v1 = __ldg(reinterpret_cast<const float4*>(xw + (size_t)s1 * DD) + lane);
        acc.x = fmaf(c0, v0.x, acc.x); acc.x = fmaf(c1, v1.x, acc.x);
        acc.y = fmaf(c0, v0.y, acc.y); acc.y = fmaf(c1, v1.y, acc.y);
        acc.z = fmaf(c0, v0.z, acc.z); acc.z = fmaf(c1, v1.z, acc.z);
        acc.w = fmaf(c0, v0.w, acc.w); acc.w = fmaf(c1, v1.w, acc.w);
    }
    if (i < end) {
        int s0 = g_srcidx[i];
        float c0 = di * g_dinv[s0];
        float4 v0 = __ldg(reinterpret_cast<const float4*>(xw + (size_t)s0 * DD) + lane);
        acc.x = fmaf(c0, v0.x, acc.x);
        acc.y = fmaf(c0, v0.y, acc.y);
        acc.z = fmaf(c0, v0.z, acc.z);
        acc.w = fmaf(c0, v0.w, acc.w);
    }
    reinterpret_cast<float4*>(outp + (size_t)w * DD)[lane] = acc;
}

// ---------------- BN stats (two-stage, fp64 partials) ----------------
__global__ __launch_bounds__(256) void k_stats1(const float* __restrict__ h) {
    __shared__ double s1[256], s2[256];
    int t = threadIdx.x;
    int d = t & 127, half = t >> 7;
    double sum = 0.0, sq = 0.0;
    for (int r = blockIdx.x * 2 + half; r < NN; r += gridDim.x * 2) {
        double v = (double)h[(size_t)r * DD + d];
        sum += v; sq += v * v;
    }
    s1[t] = sum; s2[t] = sq;
    __syncthreads();
    if (t < 128) {
        g_bsum[blockIdx.x * DD + t] = s1[t] + s1[t + 128];
        g_bsq [blockIdx.x * DD + t] = s2[t] + s2[t + 128];
    }
}

__global__ void k_stats2(const float* __restrict__ gw, const float* __restrict__ be, int nb) {
    int d = threadIdx.x; // 128 threads
    double sum = 0.0, sq = 0.0;
    for (int b = 0; b < nb; b++) { sum += g_bsum[b * DD + d]; sq += g_bsq[b * DD + d]; }
    double mu = sum / (double)NN;
    double var = sq / (double)NN - mu * mu;
    float inv = (float)(1.0 / sqrt(var + 1e-5));
    float scl = gw[d] * inv;
    g_scale[d] = scl;
    g_shift[d] = be[d] - (float)mu * scl;
}

// ---------------- final BN apply (no activation on last layer) ----------------
__global__ void k_apply(float* __restrict__ h) {
    int idx = blockIdx.x * blockDim.x + threadIdx.x;
    if (idx < NN * DD) {
        int d = idx & 127;
        h[idx] = h[idx] * g_scale[d] + g_shift[d];
    }
}

// ---------------- host launcher ----------------
extern "C" void kernel_launch(void* const* d_in, const int* in_sizes, int n_in,
                              void* d_out, int out_size) {
    const float* x   = (const float*)d_in[0];
    const void*  ei  = d_in[1];
    const float* w0  = (const float*)d_in[2];
    const float* g0  = (const float*)d_in[4];
    const float* be0 = (const float*)d_in[5];
    const float* w1  = (const float*)d_in[6];
    const float* g1  = (const float*)d_in[8];
    const float* be1 = (const float*)d_in[9];
    const float* w2  = (const float*)d_in[10];
    const float* g2  = (const float*)d_in[12];
    const float* be2 = (const float*)d_in[13];
    float* out = (float*)d_out;

    float *xw, *h, *scl, *shf;
    cudaGetSymbolAddress((void**)&xw,  g_xw);
    cudaGetSymbolAddress((void**)&h,   g_h);
    cudaGetSymbolAddress((void**)&scl, g_scale);
    cudaGetSymbolAddress((void**)&shf, g_shift);

    const int TB = 256;
    int gbN = (NN + TB - 1) / TB;
    int gbE = (EE + TB - 1) / TB;
    int gbG = (NN + 127) / 128;            // 469 GEMM row tiles
    int gbA = (NN * 32 + TB - 1) / TB;     // warp per node
    int gbP = (NN * DD + TB - 1) / TB;

    // graph structure (recomputed each call — deterministic work)
    k_detect<<<1, 32>>>(ei);
    k_zero_cnt<<<gbN, TB>>>();
    k_hist<<<gbE, TB>>>(ei);
    k_dinv<<<gbN, TB>>>();
    k_scan1<<<SCANB, 1024>>>();
    k_scan2<<<1, 32>>>(SCANB);
    k_scan3<<<gbN, TB>>>();
    k_fill<<<gbE, TB>>>(ei);

    // layer 0: GEMM(x) -> xw ; agg -> h ; stats -> scale/shift
    k_gemm<<<gbG, TB>>>(x, w0, xw, nullptr, nullptr, 0);
    k_agg<<<gbA, TB>>>(xw, h);
    k_stats1<<<SBLK, TB>>>(h);
    k_stats2<<<1, DD>>>(g0, be0, SBLK);

    // layer 1: GEMM(BN0+LeakyReLU fused into A-load of h) -> xw ; agg -> h
    k_gemm<<<gbG, TB>>>(h, w1, xw, scl, shf, 1);
    k_agg<<<gbA, TB>>>(xw, h);
    k_stats1<<<SBLK, TB>>>(h);
    k_stats2<<<1, DD>>>(g1, be1, SBLK);

    // layer 2: GEMM(BN1+LeakyReLU fused) -> xw ; agg -> out ; BN2 applied standalone
    k_gemm<<<gbG, TB>>>(h, w2, xw, scl, shf, 1);
    k_agg<<<gbA, TB>>>(xw, out);
    k_stats1<<<SBLK, TB>>>(out);
    k_stats2<<<1, DD>>>(g2, be2, SBLK);
    k_apply<<<gbP, TB>>>(out);
}

// round 2
// speedup vs baseline: 1.4866x; 1.4866x over previous
#include <cuda_runtime.h>
#include <cstdint>

#define NN 60000
#define EE 600000
#define DD 128
#define SLOPE 0.01f
#define SBLK 512
#define SCANB 59

typedef unsigned long long ull;

// ---------------- device scratch (static, no allocation) ----------------
__device__ int   g_is64;
__device__ int   g_cnt[NN];
__device__ int   g_incl[NN];
__device__ int   g_part[64];
__device__ int   g_rowstart[NN + 1];
__device__ int   g_next[NN];
__device__ int2  g_edge[EE];          // (src, __float_as_int(dinv[src]))
__device__ float g_dinv[NN];
__device__ float g_xw[(size_t)NN * DD];
__device__ float g_h[(size_t)NN * DD];
__device__ double g_bsum[SBLK * DD];
__device__ double g_bsq[SBLK * DD];
__device__ float g_scale[DD];
__device__ float g_shift[DD];

// packed f32x2 FMA: d = a*b + d  (2 fp32 lanes per instruction, sm_103a FFMA2)
#define FMA2(d, a, b) asm("fma.rn.f32x2 %0, %1, %2, %0;" : "+l"(d) : "l"(a), "l"(b))

// ---------------- init: edge dtype detect + zero counters ----------------
__global__ void k_init(const void* ei) {
    int i = blockIdx.x * blockDim.x + threadIdx.x;
    if (i < NN) g_cnt[i] = 0;
    if (i == 0) {
        const long long* q = (const long long*)ei;
        int ok = 1;
        for (int j = 0; j < 256; j++) {
            long long v = q[j];
            if (v < 0 || v >= NN) { ok = 0; break; }
        }
        g_is64 = ok;
    }
}

__device__ __forceinline__ int edge_at(const void* p, int idx, int is64) {
    return is64 ? (int)((const long long*)p)[idx] : ((const int*)p)[idx];
}

__global__ void k_hist(const void* ei) {
    int e = blockIdx.x * blockDim.x + threadIdx.x;
    if (e < EE) {
        int d = edge_at(ei, EE + e, g_is64);
        atomicAdd(&g_cnt[d], 1);
    }
}

__global__ void k_dinv() {
    int i = blockIdx.x * blockDim.x + threadIdx.x;
    if (i < NN) g_dinv[i] = rsqrtf((float)(g_cnt[i] + 1)); // +1 self loop
}

__global__ void k_scan1() {
    __shared__ int s[1024];
    int i = blockIdx.x * 1024 + threadIdx.x;
    int x = (i < NN) ? g_cnt[i] : 0;
    s[threadIdx.x] = x;
    __syncthreads();
    for (int off = 1; off < 1024; off <<= 1) {
        int v = (threadIdx.x >= off) ? s[threadIdx.x - off] : 0;
        __syncthreads();
        s[threadIdx.x] += v;
        __syncthreads();
    }
    if (i < NN) g_incl[i] = s[threadIdx.x];
    if (threadIdx.x == 1023) g_part[blockIdx.x] = s[1023];
}

__global__ void k_scan2(int nb) {
    if (threadIdx.x == 0 && blockIdx.x == 0) {
        int run = 0;
        for (int b = 0; b < nb; b++) { int t = g_part[b]; g_part[b] = run; run += t; }
    }
}

__global__ void k_scan3() {
    int i = blockIdx.x * blockDim.x + threadIdx.x;
    if (i < NN) {
        int rs = g_incl[i] - g_cnt[i] + g_part[i >> 10];
        g_rowstart[i] = rs;
        g_next[i] = rs;
    }
    if (i == 0) g_rowstart[NN] = EE;
}

__global__ void k_fill(const void* ei) {
    int e = blockIdx.x * blockDim.x + threadIdx.x;
    if (e < EE) {
        int is64 = g_is64;
        int s = edge_at(ei, e, is64);
        int d = edge_at(ei, EE + e, is64);
        int pos = atomicAdd(&g_next[d], 1);
        g_edge[pos] = make_int2(s, __float_as_int(g_dinv[s]));
    }
}

// ---------------- GEMM: C[M,128] = f(A)[M,128] @ W[128,128], FFMA2 ----------
// f(A) optionally applies per-feature affine (prev BN) + LeakyReLU at A-load.
__global__ __launch_bounds__(256, 2) void k_gemm(
    const float* __restrict__ A, const float* __restrict__ W,
    float* __restrict__ C,
    const float* __restrict__ scale, const float* __restrict__ shift, int act)
{
    __shared__ float As2[8][256];  // duplicated pairs: As2[k][2r]=As2[k][2r+1]=A[r0+r][k0+k]
    __shared__ float Ws[8][128];

    int t = threadIdx.x;
    int r0 = blockIdx.x * 128;
    int ty = t >> 4, tx = t & 15;           // 16x16 thread grid; 8x8 output per thread
    int arow = t >> 1, ahalf = t & 1;       // A tile fill: 128 rows x 8 cols
    int wrow = t >> 5, wcol = (t & 31) * 4; // W tile fill: 8 rows x 128 cols

    ull acc2[8][4];
#pragma unroll
    for (int i = 0; i < 8; i++)
#pragma unroll
        for (int j = 0; j < 4; j++) acc2[i][j] = 0ull;

    // prefetch first tiles
    float4 av = make_float4(0.f, 0.f, 0.f, 0.f);
    int gr = r0 + arow;
    if (gr < NN)
        av = *reinterpret_cast<const float4*>(A + (size_t)gr * DD + ahalf * 4);
    float4 wv = *reinterpret_cast<const float4*>(W + (size_t)wrow * DD + wcol);

    for (int k0 = 0; k0 < 128; k0 += 8) {
        // transform + stage to smem
        float4 ta = av;
        int c0 = k0 + ahalf * 4;
        if (scale) {
            ta.x = ta.x * scale[c0 + 0] + shift[c0 + 0];
            ta.y = ta.y * scale[c0 + 1] + shift[c0 + 1];
            ta.z = ta.z * scale[c0 + 2] + shift[c0 + 2];
            ta.w = ta.w * scale[c0 + 3] + shift[c0 + 3];
            if (act) {
                ta.x = ta.x >= 0.f ? ta.x : SLOPE * ta.x;
                ta.y = ta.y >= 0.f ? ta.y : SLOPE * ta.y;
                ta.z = ta.z >= 0.f ? ta.z : SLOPE * ta.z;
                ta.w = ta.w >= 0.f ? ta.w : SLOPE * ta.w;
            }
        }
        *reinterpret_cast<float2*>(&As2[ahalf * 4 + 0][2 * arow]) = make_float2(ta.x, ta.x);
        *reinterpret_cast<float2*>(&As2[ahalf * 4 + 1][2 * arow]) = make_float2(ta.y, ta.y);
        *reinterpret_cast<float2*>(&As2[ahalf * 4 + 2][2 * arow]) = make_float2(ta.z, ta.z);
        *reinterpret_cast<float2*>(&As2[ahalf * 4 + 3][2 * arow]) = make_float2(ta.w, ta.w);
        *reinterpret_cast<float4*>(&Ws[wrow][wcol]) = wv;
        __syncthreads();

        // prefetch next k0 tile while computing
        if (k0 + 8 < 128) {
            if (gr < NN)
                av = *reinterpret_cast<const float4*>(A + (size_t)gr * DD + (k0 + 8) + ahalf * 4);
            wv = *reinterpret_cast<const float4*>(W + (size_t)(k0 + 8 + wrow) * DD + wcol);
        }

#pragma unroll
        for (int kk = 0; kk < 8; kk++) {
            ulonglong2 pa0 = *reinterpret_cast<const ulonglong2*>(&As2[kk][ty * 16 + 0]);
            ulonglong2 pa1 = *reinterpret_cast<const ulonglong2*>(&As2[kk][ty * 16 + 4]);
            ulonglong2 pa2 = *reinterpret_cast<const ulonglong2*>(&As2[kk][ty * 16 + 8]);
            ulonglong2 pa3 = *reinterpret_cast<const ulonglong2*>(&As2[kk][ty * 16 + 12]);
            ulonglong2 pb0 = *reinterpret_cast<const ulonglong2*>(&Ws[kk][tx * 8 + 0]);
            ulonglong2 pb1 = *reinterpret_cast<const ulonglong2*>(&Ws[kk][tx * 8 + 4]);
            ull a2[8] = {pa0.x, pa0.y, pa1.x, pa1.y, pa2.x, pa2.y, pa3.x, pa3.y};
            ull b2[4] = {pb0.x, pb0.y, pb1.x, pb1.y};
#pragma unroll
            for (int i = 0; i < 8; i++) {
                FMA2(acc2[i][0], a2[i], b2[0]);
                FMA2(acc2[i][1], a2[i], b2[1]);
                FMA2(acc2[i][2], a2[i], b2[2]);
                FMA2(acc2[i][3], a2[i], b2[3]);
            }
        }
        __syncthreads();
    }

#pragma unroll
    for (int i = 0; i < 8; i++) {
        int orow = r0 + ty * 8 + i;
        if (orow < NN) {
            ulonglong2 u0 = make_ulonglong2(acc2[i][0], acc2[i][1]);
            ulonglong2 u1 = make_ulonglong2(acc2[i][2], acc2[i][3]);
            *reinterpret_cast<ulonglong2*>(C + (size_t)orow * DD + tx * 8 + 0) = u0;
            *reinterpret_cast<ulonglong2*>(C + (size_t)orow * DD + tx * 8 + 4) = u1;
        }
    }
}

// ---------------- aggregation: warp per node, CSR gather, unroll 4 ----------
__global__ __launch_bounds__(256) void k_agg(
    const float* __restrict__ xw, float* __restrict__ outp)
{
    int w = (blockIdx.x * blockDim.x + threadIdx.x) >> 5;
    int lane = threadIdx.x & 31;
    if (w >= NN) return;
    float di = g_dinv[w];

    float4 acc = __ldg(reinterpret_cast<const float4*>(xw + (size_t)w * DD) + lane);
    float cself = di * di;
    acc.x *= cself; acc.y *= cself; acc.z *= cself; acc.w *= cself;

    int beg = g_rowstart[w], end = g_rowstart[w + 1];
    int i = beg;
    for (; i + 3 < end; i += 4) {
        int2 e0 = __ldg(&g_edge[i + 0]);
        int2 e1 = __ldg(&g_edge[i + 1]);
        int2 e2 = __ldg(&g_edge[i + 2]);
        int2 e3 = __ldg(&g_edge[i + 3]);
        float4 v0 = __ldg(reinterpret_cast<const float4*>(xw + (size_t)e0.x * DD) + lane);
        float4 v1 = __ldg(reinterpret_cast<const float4*>(xw + (size_t)e1.x * DD) + lane);
        float4 v2 = __ldg(reinterpret_cast<const float4*>(xw + (size_t)e2.x * DD) + lane);
        float4 v3 = __ldg(reinterpret_cast<const float4*>(xw + (size_t)e3.x * DD) + lane);
        float c0 = di * __int_as_float(e0.y);
        float c1 = di * __int_as_float(e1.y);
        float c2 = di * __int_as_float(e2.y);
        float c3 = di * __int_as_float(e3.y);
        acc.x = fmaf(c0, v0.x, acc.x); acc.y = fmaf(c0, v0.y, acc.y);
        acc.z = fmaf(c0, v0.z, acc.z); acc.w = fmaf(c0, v0.w, acc.w);
        acc.x = fmaf(c1, v1.x, acc.x); acc.y = fmaf(c1, v1.y, acc.y);
        acc.z = fmaf(c1, v1.z, acc.z); acc.w = fmaf(c1, v1.w, acc.w);
        acc.x = fmaf(c2, v2.x, acc.x); acc.y = fmaf(c2, v2.y, acc.y);
        acc.z = fmaf(c2, v2.z, acc.z); acc.w = fmaf(c2, v2.w, acc.w);
        acc.x = fmaf(c3, v3.x, acc.x); acc.y = fmaf(c3, v3.y, acc.y);
        acc.z = fmaf(c3, v3.z, acc.z); acc.w = fmaf(c3, v3.w, acc.w);
    }
    for (; i < end; i++) {
        int2 e0 = __ldg(&g_edge[i]);
        float c0 = di * __int_as_float(e0.y);
        float4 v0 = __ldg(reinterpret_cast<const float4*>(xw + (size_t)e0.x * DD) + lane);
        acc.x = fmaf(c0, v0.x, acc.x); acc.y = fmaf(c0, v0.y, acc.y);
        acc.z = fmaf(c0, v0.z, acc.z); acc.w = fmaf(c0, v0.w, acc.w);
    }
    reinterpret_cast<float4*>(outp + (size_t)w * DD)[lane] = acc;
}

// ---------------- BN stats (two-stage, fp64 partials) ----------------
__global__ __launch_bounds__(256) void k_stats1(const float* __restrict__ h) {
    __shared__ double s1[256], s2[256];
    int t = threadIdx.x;
    int d = t & 127, half = t >> 7;
    double sum = 0.0, sq = 0.0;
    for (int r = blockIdx.x * 2 + half; r < NN; r += gridDim.x * 2) {
        double v = (double)h[(size_t)r * DD + d];
        sum += v; sq += v * v;
    }
    s1[t] = sum; s2[t] = sq;
    __syncthreads();
    if (t < 128) {
        g_bsum[blockIdx.x * DD + t] = s1[t] + s1[t + 128];
        g_bsq [blockIdx.x * DD + t] = s2[t] + s2[t + 128];
    }
}

__global__ void k_stats2(const float* __restrict__ gw, const float* __restrict__ be, int nb) {
    int d = threadIdx.x; // 128 threads
    double sum = 0.0, sq = 0.0;
    for (int b = 0; b < nb; b++) { sum += g_bsum[b * DD + d]; sq += g_bsq[b * DD + d]; }
    double mu = sum / (double)NN;
    double var = sq / (double)NN - mu * mu;
    float inv = (float)(1.0 / sqrt(var + 1e-5));
    float scl = gw[d] * inv;
    g_scale[d] = scl;
    g_shift[d] = be[d] - (float)mu * scl;
}

// ---------------- final BN apply ----------------
__global__ void k_apply(float* __restrict__ h) {
    int idx = blockIdx.x * blockDim.x + threadIdx.x;
    if (idx < NN * DD) {
        int d = idx & 127;
        h[idx] = h[idx] * g_scale[d] + g_shift[d];
    }
}

// ---------------- host launcher ----------------
extern "C" void kernel_launch(void* const* d_in, const int* in_sizes, int n_in,
                              void* d_out, int out_size) {
    const float* x   = (const float*)d_in[0];
    const void*  ei  = d_in[1];
    const float* w0  = (const float*)d_in[2];
    const float* g0  = (const float*)d_in[4];
    const float* be0 = (const float*)d_in[5];
    const float* w1  = (const float*)d_in[6];
    const float* g1  = (const float*)d_in[8];
    const float* be1 = (const float*)d_in[9];
    const float* w2  = (const float*)d_in[10];
    const float* g2  = (const float*)d_in[12];
    const float* be2 = (const float*)d_in[13];
    float* out = (float*)d_out;

    float *xw, *h, *scl, *shf;
    cudaGetSymbolAddress((void**)&xw,  g_xw);
    cudaGetSymbolAddress((void**)&h,   g_h);
    cudaGetSymbolAddress((void**)&scl, g_scale);
    cudaGetSymbolAddress((void**)&shf, g_shift);

    const int TB = 256;
    int gbN = (NN + TB - 1) / TB;
    int gbE = (EE + TB - 1) / TB;
    int gbG = (NN + 127) / 128;
    int gbA = (NN * 32 + TB - 1) / TB;
    int gbP = (NN * DD + TB - 1) / TB;

    // graph structure (recomputed each call — deterministic)
    k_init<<<gbN, TB>>>(ei);
    k_hist<<<gbE, TB>>>(ei);
    k_dinv<<<gbN, TB>>>();
    k_scan1<<<SCANB, 1024>>>();
    k_scan2<<<1, 32>>>(SCANB);
    k_scan3<<<gbN, TB>>>();
    k_fill<<<gbE, TB>>>(ei);

    // layer 0
    k_gemm<<<gbG, TB>>>(x, w0, xw, nullptr, nullptr, 0);
    k_agg<<<gbA, TB>>>(xw, h);
    k_stats1<<<SBLK, TB>>>(h);
    k_stats2<<<1, DD>>>(g0, be0, SBLK);

    // layer 1 (BN0 + LeakyReLU fused into A-load)
    k_gemm<<<gbG, TB>>>(h, w1, xw, scl, shf, 1);
    k_agg<<<gbA, TB>>>(xw, h);
    k_stats1<<<SBLK, TB>>>(h);
    k_stats2<<<1, DD>>>(g1, be1, SBLK);

    // layer 2 (BN1 + LeakyReLU fused), final BN applied standalone
    k_gemm<<<gbG, TB>>>(h, w2, xw, scl, shf, 1);
    k_agg<<<gbA, TB>>>(xw, out);
    k_stats1<<<SBLK, TB>>>(out);
    k_stats2<<<1, DD>>>(g2, be2, SBLK);
    k_apply<<<gbP, TB>>>(out);
}